// round 17
// baseline (speedup 1.0000x reference)
#include <cuda_runtime.h>
#include <cuda_fp16.h>
#include <cstdint>
#include <math.h>

#define NE 8
#define NTOK 16384
#define DIM 1024
#define FF 2048
#define NKT1 (DIM / 64)
#define NKT2 (FF / 64)

// ---------------- scratch (device globals; no allocation) ----------------
__device__ int    g_counts[NE];
__device__ int    g_tok[NE * NTOK];
__device__ float  g_cw[NE * NTOK];
__device__ int    g_sE[2 * NTOK];
__device__ int    g_sP[2 * NTOK];
__device__ __half g_H[(size_t)2 * NTOK * FF];        // hidden activations (fp16)
__device__ float  g_O[(size_t)2 * NTOK * DIM];       // per-slot scaled expert outputs (fp32)
__device__ __half g_xh[(size_t)NTOK * DIM];          // fp16 x
__device__ __half g_w1h[(size_t)NE * FF * DIM];
__device__ __half g_w2h[(size_t)NE * DIM * FF];
__device__ __half g_w3h[(size_t)NE * FF * DIM];

// ---------------- helpers ----------------
__device__ __forceinline__ uint32_t ph2(float a, float b) {
    __half2 h = __floats2half2_rn(a, b);
    return *(uint32_t*)&h;
}

static __device__ __forceinline__ uint32_t smem_u32(const void* p) {
    uint32_t a;
    asm("{ .reg .u64 t; cvta.to.shared.u64 t, %1; cvt.u32.u64 %0, t; }" : "=r"(a) : "l"(p));
    return a;
}

__device__ __forceinline__ void mma16(float* c, const uint32_t* a, const uint32_t* b) {
    asm volatile(
        "mma.sync.aligned.m16n8k16.row.col.f32.f16.f16.f32 "
        "{%0,%1,%2,%3},{%4,%5,%6,%7},{%8,%9},{%0,%1,%2,%3};"
        : "+f"(c[0]), "+f"(c[1]), "+f"(c[2]), "+f"(c[3])
        : "r"(a[0]), "r"(a[1]), "r"(a[2]), "r"(a[3]), "r"(b[0]), "r"(b[1]));
}

#define LDSM4(r0_, r1_, r2_, r3_, addr)                                        \
    asm volatile("ldmatrix.sync.aligned.m8n8.x4.shared.b16 {%0,%1,%2,%3}, [%4];" \
        : "=r"(r0_), "=r"(r1_), "=r"(r2_), "=r"(r3_) : "r"(addr))

__device__ __forceinline__ void cpa16(uint32_t dst, const void* src, uint32_t nbytes) {
    asm volatile("cp.async.cg.shared.global [%0], [%1], 16, %2;"
                 :: "r"(dst), "l"(src), "r"(nbytes) : "memory");
}
#define CP_COMMIT() asm volatile("cp.async.commit_group;" ::: "memory")
#define CP_WAIT1()  asm volatile("cp.async.wait_group 1;" ::: "memory")

// 128B-row swizzle (64 halfs/row): row r, 16B chunk c (0..7) -> phys chunk c^(r&7).
__device__ __forceinline__ uint32_t swb32(int r, int c) {
    return (uint32_t)(r * 128 + ((c ^ r) & 7) * 16);
}

// ---------------- fused prep: 3 weight conversions + gating + x->fp16 ----------------
__global__ void prep_kernel(const float* __restrict__ x,  const float* __restrict__ gw,
                            const float* __restrict__ w1, const float* __restrict__ w2,
                            const float* __restrict__ w3, int n8) {
    if (blockIdx.y < 3) {
        // weight conversion slice
        if (blockIdx.y == 0 && blockIdx.x == 0 && threadIdx.x < NE)
            g_counts[threadIdx.x] = 0;
        int i = blockIdx.x * blockDim.x + threadIdx.x;
        if (i >= n8) return;
        const float* src = (blockIdx.y == 0) ? w1 : (blockIdx.y == 1) ? w2 : w3;
        __half* dst = (blockIdx.y == 0) ? g_w1h : (blockIdx.y == 1) ? g_w2h : g_w3h;
        float4 a = ((const float4*)src)[2 * i];
        float4 b = ((const float4*)src)[2 * i + 1];
        uint4 u;
        u.x = ph2(a.x, a.y); u.y = ph2(a.z, a.w);
        u.z = ph2(b.x, b.y); u.w = ph2(b.z, b.w);
        ((uint4*)dst)[i] = u;
        return;
    }
    // gate slice
    if (blockIdx.x >= NTOK / 8) return;
    int warp = threadIdx.x >> 5;
    int lane = threadIdx.x & 31;
    int token = blockIdx.x * 8 + warp;

    const float* xr = x + (size_t)token * DIM;
    float xv[32];
#pragma unroll
    for (int j = 0; j < 32; j++) xv[j] = xr[j * 32 + lane];

    __half* xh = g_xh + (size_t)token * DIM;
#pragma unroll
    for (int j = 0; j < 32; j++) xh[j * 32 + lane] = __float2half_rn(xv[j]);

    float logits[NE];
#pragma unroll
    for (int e = 0; e < NE; e++) {
        const float* g = gw + e * DIM;
        float s = 0.0f;
#pragma unroll
        for (int j = 0; j < 32; j++) s += xv[j] * g[j * 32 + lane];
#pragma unroll
        for (int o = 16; o; o >>= 1) s += __shfl_xor_sync(0xffffffffu, s, o);
        logits[e] = s;
    }

    if (lane == 0) {
        int i1 = 0;
#pragma unroll
        for (int e = 1; e < NE; e++)
            if (logits[e] > logits[i1]) i1 = e;
        int i2 = -1;
#pragma unroll
        for (int e = 0; e < NE; e++) {
            if (e == i1) continue;
            if (i2 < 0 || logits[e] > logits[i2]) i2 = e;
        }
        float p1 = 1.0f / (1.0f + __expf(logits[i2] - logits[i1]));
        float p2 = 1.0f - p1;
        int s1 = atomicAdd(&g_counts[i1], 1);
        g_tok[i1 * NTOK + s1] = token;
        g_cw[i1 * NTOK + s1]  = p1;
        int s2 = atomicAdd(&g_counts[i2], 1);
        g_tok[i2 * NTOK + s2] = token;
        g_cw[i2 * NTOK + s2]  = p2;
        g_sE[2 * token] = i1;  g_sP[2 * token] = s1;
        g_sE[2 * token + 1] = i2;  g_sP[2 * token + 1] = s2;
    }
}

// ---------------- tile scheduler (inline prefix: also returns expert offset) ----------------
__device__ __forceinline__ bool find_tile(int bx, int& e, int& tile, int& cnt, int& offs) {
    int acc = 0, off = 0;
    e = -1;
#pragma unroll
    for (int ee = 0; ee < NE; ee++) {
        int c = g_counts[ee];
        int t = (c + 127) >> 7;
        if (e < 0 && bx < acc + t) { e = ee; tile = bx - acc; cnt = c; offs = off; }
        acc += t;
        off += c;
    }
    return e >= 0;
}

// dynamic SMEM: [0:512) stok, [512:1024) scw, stages at 1024 + s*32768
#define STG_BASE 1024
#define STG_SZ   32768
#define SMEM_BYTES (STG_BASE + 3 * STG_SZ)

// ---------------- kernel 3: GEMM1 (x@w1^T, x@w3^T) -> silu*mul -> H(fp16) ----------------
__global__ __launch_bounds__(128, 2) void gemm1_kernel() {
    extern __shared__ char dsm[];
    int e, tile, cnt, offs;
    if (!find_tile(blockIdx.x, e, tile, cnt, offs)) return;
    int n0 = blockIdx.y * 64;

    int tid = threadIdx.x;
    int* stok = (int*)dsm;
    {
        int i = tile * 128 + tid;
        stok[tid] = (i < cnt) ? g_tok[e * NTOK + i] : -1;
    }
    __syncthreads();

    int warp = tid >> 5, lane = tid & 31;
    int wm = warp >> 1, wn = warp & 1;
    uint32_t sb = smem_u32(dsm);

    const __half* asrc[8]; uint32_t asz[8], adst[8];
#pragma unroll
    for (int j = 0; j < 8; j++) {
        int idx = tid + j * 128;
        int r = idx >> 3, c = idx & 7;
        int t = stok[r];
        asrc[j] = g_xh + (size_t)(t < 0 ? 0 : t) * DIM + c * 8;
        asz[j]  = (t < 0) ? 0u : 16u;
        adst[j] = swb32(r, c);
    }
    const __half* b1src[4]; const __half* b3src[4]; uint32_t bdst[4];
#pragma unroll
    for (int j = 0; j < 4; j++) {
        int idx = tid + j * 128;
        int r = idx >> 3, c = idx & 7;
        b1src[j] = g_w1h + (size_t)e * FF * DIM + (size_t)(n0 + r) * DIM + c * 8;
        b3src[j] = g_w3h + (size_t)e * FF * DIM + (size_t)(n0 + r) * DIM + c * 8;
        bdst[j]  = swb32(r, c);
    }
    auto issue_stage = [&](int s, int kt) {
        uint32_t base = sb + STG_BASE + s * STG_SZ;
        int k0 = kt * 64;
#pragma unroll
        for (int j = 0; j < 8; j++) cpa16(base + adst[j], asrc[j] + k0, asz[j]);
#pragma unroll
        for (int j = 0; j < 4; j++) cpa16(base + 16384 + bdst[j], b1src[j] + k0, 16);
#pragma unroll
        for (int j = 0; j < 4; j++) cpa16(base + 24576 + bdst[j], b3src[j] + k0, 16);
    };

    int arow = (((lane >> 3) & 1) << 3) + (lane & 7);
    int acol = lane >> 4;
    int brow = (((lane >> 4) & 1) << 3) + (lane & 7);
    int bcol = (lane >> 3) & 1;
    uint32_t offA[4][4], offB[2][4];
#pragma unroll
    for (int mt = 0; mt < 4; mt++)
#pragma unroll
        for (int kki = 0; kki < 4; kki++)
            offA[mt][kki] = swb32(wm * 64 + mt * 16 + arow, kki * 2 + acol);
#pragma unroll
    for (int p = 0; p < 2; p++)
#pragma unroll
        for (int kki = 0; kki < 4; kki++)
            offB[p][kki] = swb32(wn * 32 + p * 16 + brow, kki * 2 + bcol);

    float acc1[4][4][4] = {};
    float acc3[4][4][4] = {};

    auto compute_stage = [&](int s) {
        uint32_t base = sb + STG_BASE + s * STG_SZ;
        uint32_t aA = base, aB1 = base + 16384, aB3 = base + 24576;
        uint32_t a[2][4][4], b1f[2][2][4], b3f[2][2][4];
        auto ldk = [&](int buf, int kki) {
#pragma unroll
            for (int mt = 0; mt < 4; mt++)
                LDSM4(a[buf][mt][0], a[buf][mt][1], a[buf][mt][2], a[buf][mt][3],
                      aA + offA[mt][kki]);
#pragma unroll
            for (int p = 0; p < 2; p++) {
                LDSM4(b1f[buf][p][0], b1f[buf][p][1], b1f[buf][p][2], b1f[buf][p][3],
                      aB1 + offB[p][kki]);
                LDSM4(b3f[buf][p][0], b3f[buf][p][1], b3f[buf][p][2], b3f[buf][p][3],
                      aB3 + offB[p][kki]);
            }
        };
        ldk(0, 0);
#pragma unroll
        for (int kki = 0; kki < 4; kki++) {
            int cur = kki & 1;
            if (kki < 3) ldk(cur ^ 1, kki + 1);
#pragma unroll
            for (int p = 0; p < 2; p++) {
#pragma unroll
                for (int mt = 0; mt < 4; mt++) {
                    mma16(acc1[mt][2 * p],     a[cur][mt], &b1f[cur][p][0]);
                    mma16(acc1[mt][2 * p + 1], a[cur][mt], &b1f[cur][p][2]);
                    mma16(acc3[mt][2 * p],     a[cur][mt], &b3f[cur][p][0]);
                    mma16(acc3[mt][2 * p + 1], a[cur][mt], &b3f[cur][p][2]);
                }
            }
        }
    };

    issue_stage(0, 0); CP_COMMIT();
    issue_stage(1, 1); CP_COMMIT();
#pragma unroll 1
    for (int kt = 0; kt < NKT1; kt++) {
        CP_WAIT1();
        __syncthreads();
        if (kt + 2 < NKT1) { issue_stage((kt + 2) % 3, kt + 2); CP_COMMIT(); }
        compute_stage(kt % 3);
    }

    // epilogue: silu(s1)*s3 -> smem stage (stride 72 halfs) -> coalesced H rows
    __syncthreads();   // stage buffers free (all warps past final compute)
    __half* hst = (__half*)(dsm + STG_BASE);
#pragma unroll
    for (int mt = 0; mt < 4; mt++) {
#pragma unroll
        for (int nt = 0; nt < 4; nt++) {
            int r0 = wm * 64 + mt * 16 + (lane >> 2);
            int cc = wn * 32 + nt * 8 + ((lane & 3) << 1);
#pragma unroll
            for (int h8 = 0; h8 < 2; h8++) {
                int r = r0 + h8 * 8;
                float s1a = acc1[mt][nt][2 * h8],     s3a = acc3[mt][nt][2 * h8];
                float s1b = acc1[mt][nt][2 * h8 + 1], s3b = acc3[mt][nt][2 * h8 + 1];
                float ha = (s1a / (1.0f + __expf(-s1a))) * s3a;
                float hb = (s1b / (1.0f + __expf(-s1b))) * s3b;
                *(__half2*)(hst + r * 72 + cc) = __floats2half2_rn(ha, hb);
            }
        }
    }
    __syncthreads();
    {
        int i = tile * 128 + tid;
        if (i < cnt) {
            uint4* dst = (uint4*)(g_H + (size_t)(offs + i) * FF + n0);
            const uint4* srcp = (const uint4*)(hst + tid * 72);
#pragma unroll
            for (int j = 0; j < 8; j++) dst[j] = srcp[j];
        }
    }
}

// ---------------- kernel 4: GEMM2 (H @ w2^T), scaled rows -> g_O (no atomics) ----------------
__global__ __launch_bounds__(128, 2) void gemm2_kernel() {
    extern __shared__ char dsm[];
    int e, tile, cnt, offs;
    if (!find_tile(blockIdx.x, e, tile, cnt, offs)) return;
    int n0 = blockIdx.y * 128;

    int tid = threadIdx.x;
    float* scw = (float*)(dsm + 512);
    {
        int i = tile * 128 + tid;
        scw[tid] = (i < cnt) ? g_cw[e * NTOK + i] : 0.0f;
    }
    __syncthreads();

    int warp = tid >> 5, lane = tid & 31;
    int wm = warp >> 1, wn = warp & 1;
    uint32_t sb = smem_u32(dsm);

    const __half* asrc[8]; uint32_t asz[8], adst[8];
    const __half* bsrc[8];
#pragma unroll
    for (int j = 0; j < 8; j++) {
        int idx = tid + j * 128;
        int r = idx >> 3, c = idx & 7;
        bool av = (tile * 128 + r) < cnt;
        asrc[j] = g_H + (size_t)(offs + tile * 128 + (av ? r : 0)) * FF + c * 8;
        asz[j]  = av ? 16u : 0u;
        adst[j] = swb32(r, c);
        bsrc[j] = g_w2h + (size_t)e * DIM * FF + (size_t)(n0 + r) * FF + c * 8;
    }
    auto issue_stage = [&](int s, int kt) {
        uint32_t base = sb + STG_BASE + s * STG_SZ;
        int k0 = kt * 64;
#pragma unroll
        for (int j = 0; j < 8; j++) cpa16(base + adst[j], asrc[j] + k0, asz[j]);
#pragma unroll
        for (int j = 0; j < 8; j++) cpa16(base + 16384 + adst[j], bsrc[j] + k0, 16);
    };

    int arow = (((lane >> 3) & 1) << 3) + (lane & 7);
    int acol = lane >> 4;
    int brow = (((lane >> 4) & 1) << 3) + (lane & 7);
    int bcol = (lane >> 3) & 1;
    uint32_t offA[4][4], offB[4][4];
#pragma unroll
    for (int mt = 0; mt < 4; mt++)
#pragma unroll
        for (int kki = 0; kki < 4; kki++)
            offA[mt][kki] = swb32(wm * 64 + mt * 16 + arow, kki * 2 + acol);
#pragma unroll
    for (int p = 0; p < 4; p++)
#pragma unroll
        for (int kki = 0; kki < 4; kki++)
            offB[p][kki] = swb32(wn * 64 + p * 16 + brow, kki * 2 + bcol);

    float acc[4][8][4] = {};

    auto compute_stage = [&](int s) {
        uint32_t base = sb + STG_BASE + s * STG_SZ;
        uint32_t aA = base, aB = base + 16384;
        uint32_t a[2][4][4], bf[2][4][4];
        auto ldk = [&](int buf, int kki) {
#pragma unroll
            for (int mt = 0; mt < 4; mt++)
                LDSM4(a[buf][mt][0], a[buf][mt][1], a[buf][mt][2], a[buf][mt][3],
                      aA + offA[mt][kki]);
#pragma unroll
            for (int p = 0; p < 4; p++)
                LDSM4(bf[buf][p][0], bf[buf][p][1], bf[buf][p][2], bf[buf][p][3],
                      aB + offB[p][kki]);
        };
        ldk(0, 0);
#pragma unroll
        for (int kki = 0; kki < 4; kki++) {
            int cur = kki & 1;
            if (kki < 3) ldk(cur ^ 1, kki + 1);
#pragma unroll
            for (int p = 0; p < 4; p++) {
#pragma unroll
                for (int mt = 0; mt < 4; mt++) {
                    mma16(acc[mt][2 * p],     a[cur][mt], &bf[cur][p][0]);
                    mma16(acc[mt][2 * p + 1], a[cur][mt], &bf[cur][p][2]);
                }
            }
        }
    };

    issue_stage(0, 0); CP_COMMIT();
    issue_stage(1, 1); CP_COMMIT();
#pragma unroll 1
    for (int kt = 0; kt < NKT2; kt++) {
        CP_WAIT1();
        __syncthreads();
        if (kt + 2 < NKT2) { issue_stage((kt + 2) % 3, kt + 2); CP_COMMIT(); }
        compute_stage(kt % 3);
    }

    // epilogue: cw*acc -> smem stage (stride 132 floats) -> coalesced g_O rows
    __syncthreads();
    float* fst = (float*)(dsm + STG_BASE);
#pragma unroll
    for (int mt = 0; mt < 4; mt++) {
#pragma unroll
        for (int nt = 0; nt < 8; nt++) {
            int r0 = wm * 64 + mt * 16 + (lane >> 2);
            int cc = wn * 64 + nt * 8 + ((lane & 3) << 1);
#pragma unroll
            for (int h8 = 0; h8 < 2; h8++) {
                int r = r0 + h8 * 8;
                float w = scw[r];
                *(float2*)(fst + r * 132 + cc) =
                    make_float2(acc[mt][nt][2 * h8] * w, acc[mt][nt][2 * h8 + 1] * w);
            }
        }
    }
    __syncthreads();
    {
        int i = tile * 128 + tid;
        if (i < cnt) {
            float4* dst = (float4*)(g_O + (size_t)(offs + i) * DIM + n0);
            const float4* srcp = (const float4*)(fst + tid * 132);
#pragma unroll
            for (int j = 0; j < 32; j++) dst[j] = srcp[j];
        }
    }
}

// ---------------- kernel 5: combine (one block per token, write-once out) ----------------
__global__ __launch_bounds__(256) void combine_kernel(float4* __restrict__ out) {
    __shared__ int soff[NE];
    if (threadIdx.x == 0) {
        int a = 0;
        for (int e = 0; e < NE; e++) { soff[e] = a; a += g_counts[e]; }
    }
    __syncthreads();
    int t = blockIdx.x;
    int d = threadIdx.x;
    size_t r1 = (size_t)(soff[g_sE[2 * t]]     + g_sP[2 * t]);
    size_t r2 = (size_t)(soff[g_sE[2 * t + 1]] + g_sP[2 * t + 1]);
    float4 a = ((const float4*)(g_O + r1 * DIM))[d];
    float4 b = ((const float4*)(g_O + r2 * DIM))[d];
    out[(size_t)t * (DIM / 4) + d] =
        make_float4(a.x + b.x, a.y + b.y, a.z + b.z, a.w + b.w);
}

// ---------------- launch (single stream, allocation-free, 4 launches) ----------------
extern "C" void kernel_launch(void* const* d_in, const int* in_sizes, int n_in,
                              void* d_out, int out_size) {
    const float* x  = (const float*)d_in[0];
    const float* gw = (const float*)d_in[1];
    const float* w1 = (const float*)d_in[2];
    const float* w2 = (const float*)d_in[3];
    const float* w3 = (const float*)d_in[4];
    float* out = (float*)d_out;

    cudaFuncSetAttribute(gemm1_kernel, cudaFuncAttributeMaxDynamicSharedMemorySize, SMEM_BYTES);
    cudaFuncSetAttribute(gemm2_kernel, cudaFuncAttributeMaxDynamicSharedMemorySize, SMEM_BYTES);

    int nw8 = NE * FF * DIM / 8;              // 2M uint4 chunks per weight
    int nblk = (nw8 + 255) / 256;             // 8192 blocks per weight slice
    prep_kernel<<<dim3(nblk, 4), 256>>>(x, gw, w1, w2, w3, nw8);

    gemm1_kernel<<<dim3(264, FF / 64), 128, SMEM_BYTES>>>();
    gemm2_kernel<<<dim3(264, DIM / 128), 128, SMEM_BYTES>>>();
    combine_kernel<<<NTOK, 256>>>((float4*)out);
}